// round 12
// baseline (speedup 1.0000x reference)
#include <cuda_runtime.h>
#include <stdint.h>

#define BATCH 128
#define NANCH 16800
#define NQ 4200               // float4 per row
#define CHUNKS 8
#define CQ 525                // float4 per chunk
#define T1 256
#define NEL 3                 // ceil(CQ / T1)
#define T2 256
#define NW1 (T1 / 32)
#define NW2 (T2 / 32)
#define NEG_RATIO 3
#define SCALE_XY 10.0f
#define SCALE_WH 5.0f
#define CAP 4096
#define XCF 1.1f              // x cutoff (softplus monotone; threshold x ~1.55)
#define HBSHIFT 13
#define HBINS 4096            // bins over x in [1.0, 16.0)
#define HBASE (0x3F800000u >> HBSHIFT)
#define CHB (HBINS / T2)      // 16
#define TIE_CAP 64
#define FLT_EPS_ 1.1920929e-07f

// Cross-block scratch (allocation-free rule: __device__ globals; zero-init; reset per replay)
__device__ float    g_row_lossb[BATCH];
__device__ float    g_row_bcepos[BATCH];
__device__ float    g_row_lossl[BATCH];
__device__ int      g_row_posn[BATCH];
__device__ int      g_cand_n[BATCH];
__device__ int      g_row_ovf[BATCH];
__device__ int      g_done = 0;
__device__ unsigned g_cand[BATCH * CAP];  // candidate x bit patterns, 2 MB

__device__ __forceinline__ float warp_sum(float v) {
    #pragma unroll
    for (int o = 16; o > 0; o >>= 1) v += __shfl_down_sync(0xFFFFFFFFu, v, o);
    return v;
}
__device__ __forceinline__ int warp_sum_i(int v) {
    #pragma unroll
    for (int o = 16; o > 0; o >>= 1) v += __shfl_down_sync(0xFFFFFFFFu, v, o);
    return v;
}
__device__ __forceinline__ int warp_suffix_incl_i(int v, int lane) {
    #pragma unroll
    for (int o = 1; o < 32; o <<= 1) {
        int u = __shfl_down_sync(0xFFFFFFFFu, v, o);
        if (lane + o < 32) v += u;
    }
    return v;
}
__device__ __forceinline__ float bce_of(float x, float y) {
    return fmaxf(x, 0.f) - x * y + __logf(1.f + __expf(-fabsf(x)));
}
__device__ __forceinline__ float softplus_pos(float x) {  // bce for negative, x>0
    return x + __logf(1.f + __expf(-x));
}
__device__ __forceinline__ unsigned fmap(unsigned b) {    // order-preserving signed-float map
    return (b & 0x80000000u) ? ~b : (b | 0x80000000u);
}

// ================= Kernel 1: wide streaming, no transcendentals on common path ========
__global__ __launch_bounds__(T1)
void od_stream(const float* __restrict__ pbboxs,
               const float* __restrict__ plabels,
               const float* __restrict__ gbboxs,
               const float* __restrict__ glabels,
               const float* __restrict__ ancs) {
    const int row  = blockIdx.y;
    const int tid  = threadIdx.x;
    const int lane = tid & 31;
    const int wid  = tid >> 5;
    const int qbase = blockIdx.x * CQ;

    __shared__ float s_wf[NW1], s_wf2[NW1];
    __shared__ int   s_wi[NW1];

    const float4* pl4 = (const float4*)(plabels + (size_t)row * NANCH);
    const float4* gl4 = (const float4*)(glabels + (size_t)row * NANCH);
    const float4* pb  = (const float4*)pbboxs + (size_t)row * NANCH;
    const float4* gb  = (const float4*)gbboxs + (size_t)row * NANCH;
    const float4* an  = (const float4*)ancs;

    // prefetch all loads up front (MLP = 6)
    float4 xv[NEL], yv[NEL];
    #pragma unroll
    for (int it = 0; it < NEL; it++) {
        const int loc = tid + it * T1;
        const int i4  = qbase + loc;
        if (loc < CQ) { xv[it] = pl4[i4]; yv[it] = gl4[i4]; }
        else { xv[it] = make_float4(0.f, 0.f, 0.f, 0.f); yv[it] = make_float4(0.f, 0.f, 0.f, 0.f); }
    }

    float acc_sl1 = 0.f, acc_bce = 0.f;
    int cnt = 0;
    #pragma unroll
    for (int it = 0; it < NEL; it++) {
        const int i4 = qbase + tid + it * T1;
        float xs[4];
        bool  cand[4];
        #pragma unroll
        for (int c = 0; c < 4; c++) {
            float x = (c == 0) ? xv[it].x : (c == 1) ? xv[it].y : (c == 2) ? xv[it].z : xv[it].w;
            float y = (c == 0) ? yv[it].x : (c == 1) ? yv[it].y : (c == 2) ? yv[it].z : yv[it].w;
            xs[c] = x;
            bool pos = (y > 0.f);            // tail lanes: y=0 -> never pos
            cand[c] = (!pos) && (x >= XCF);  // tail lanes: x=0 -> never cand
            if (pos) {                       // rare (~2%)
                acc_bce += bce_of(x, y);
                const int i = (i4 << 2) + c;
                float4 p = pb[i];
                float4 g = gb[i];
                float4 a = an[i];
                float inv_az = 1.f / a.z;
                float inv_aw = 1.f / a.w;
                float d0 = p.x - SCALE_XY * (g.x - a.x) * inv_az;
                float d1 = p.y - SCALE_XY * (g.y - a.y) * inv_aw;
                float d2 = p.z - SCALE_WH * __logf(g.z * inv_az);
                float d3 = p.w - SCALE_WH * __logf(g.w * inv_aw);
                float sl1 = 0.f, ad;
                ad = fabsf(d0); sl1 += (ad < 1.f) ? 0.5f * d0 * d0 : ad - 0.5f;
                ad = fabsf(d1); sl1 += (ad < 1.f) ? 0.5f * d1 * d1 : ad - 0.5f;
                ad = fabsf(d2); sl1 += (ad < 1.f) ? 0.5f * d2 * d2 : ad - 0.5f;
                ad = fabsf(d3); sl1 += (ad < 1.f) ? 0.5f * d3 * d3 : ad - 0.5f;
                acc_sl1 += sl1;
                cnt++;
            }
        }
        // warp-aggregated candidate compaction: ONE global atomic per warp-iter
        unsigned m0 = __ballot_sync(0xFFFFFFFFu, cand[0]);
        unsigned m1 = __ballot_sync(0xFFFFFFFFu, cand[1]);
        unsigned m2 = __ballot_sync(0xFFFFFFFFu, cand[2]);
        unsigned m3 = __ballot_sync(0xFFFFFFFFu, cand[3]);
        int wcnt = __popc(m0) + __popc(m1) + __popc(m2) + __popc(m3);
        if (wcnt > 0) {
            int base = 0;
            if (lane == 0) base = atomicAdd(&g_cand_n[row], wcnt);
            base = __shfl_sync(0xFFFFFFFFu, base, 0);
            unsigned* dst = g_cand + (size_t)row * CAP;
            const unsigned lmask = (1u << lane) - 1u;
            int off = base;
            if (cand[0]) { int pi = off + __popc(m0 & lmask); if (pi < CAP) dst[pi] = __float_as_uint(xs[0]); else g_row_ovf[row] = 1; }
            off += __popc(m0);
            if (cand[1]) { int pi = off + __popc(m1 & lmask); if (pi < CAP) dst[pi] = __float_as_uint(xs[1]); else g_row_ovf[row] = 1; }
            off += __popc(m1);
            if (cand[2]) { int pi = off + __popc(m2 & lmask); if (pi < CAP) dst[pi] = __float_as_uint(xs[2]); else g_row_ovf[row] = 1; }
            off += __popc(m2);
            if (cand[3]) { int pi = off + __popc(m3 & lmask); if (pi < CAP) dst[pi] = __float_as_uint(xs[3]); else g_row_ovf[row] = 1; }
        }
    }

    // row scalar accumulation: block reduce -> 3 global atomics
    {
        float w1 = warp_sum(acc_sl1);
        float w2 = warp_sum(acc_bce);
        int   w3 = warp_sum_i(cnt);
        if (lane == 0) { s_wf[wid] = w1; s_wf2[wid] = w2; s_wi[wid] = w3; }
    }
    __syncthreads();
    if (tid == 0) {
        float s1 = 0.f, s2 = 0.f; int s3 = 0;
        #pragma unroll
        for (int i = 0; i < NW1; i++) { s1 += s_wf[i]; s2 += s_wf2[i]; s3 += s_wi[i]; }
        if (s1 != 0.f) atomicAdd(&g_row_lossb[row], s1);
        if (s2 != 0.f) atomicAdd(&g_row_bcepos[row], s2);
        if (s3 != 0)   atomicAdd(&g_row_posn[row], s3);
    }
}

// ================= Kernel 2: per-row exact top-K selector + final reduce ==============
__global__ __launch_bounds__(T2)
void od_select(const float* __restrict__ plabels,
               const float* __restrict__ glabels,
               float* __restrict__ out, int out_size) {
    const int row  = blockIdx.x;
    const int tid  = threadIdx.x;
    const int lane = tid & 31;
    const int wid  = tid >> 5;

    __shared__ int      s_hist[HBINS];      // 16 KB
    __shared__ unsigned s_tie[TIE_CAP];
    __shared__ float    s_wf[NW2];
    __shared__ int      s_wi[NW2], s_wsuf[NW2];
    __shared__ float    s_top;
    __shared__ int      s_tn, s_tbin, s_last;
    __shared__ unsigned s_lo, s_hi;
    __shared__ float    s_red[NW2 * 3];

    const int pos_num = g_row_posn[row];
    const int M       = g_cand_n[row];
    const int ovf     = g_row_ovf[row];
    int K = NEG_RATIO * pos_num;
    if (K > NANCH) K = NANCH;

    if (tid == 0) { s_top = 0.f; s_tn = 0; s_tbin = 0; }

    if (K > 0) {
        if (!ovf && M <= CAP && M >= K) {
            // ---- Fast path: histogram select on candidate x-bits ----
            #pragma unroll
            for (int j = 0; j < CHB; j++) s_hist[tid + j * T2] = 0;
            __syncthreads();

            unsigned v[CAP / T2];  // 16
            const unsigned* src = g_cand + (size_t)row * CAP;
            #pragma unroll
            for (int j = 0; j < CAP / T2; j++) {
                const int idx = tid + j * T2;
                unsigned u = 0u;
                if (idx < M) {
                    u = src[idx];
                    unsigned bin = (u >> HBSHIFT) - HBASE;
                    if (bin > HBINS - 1) bin = HBINS - 1;
                    atomicAdd(&s_hist[bin], 1);
                }
                v[j] = u;
            }
            __syncthreads();

            // cooperative suffix-scan over 4096 bins (16 contiguous bins/thread)
            const int base = tid * CHB;
            int lc[CHB];
            int tot = 0;
            #pragma unroll
            for (int j = 0; j < CHB; j++) { lc[j] = s_hist[base + j]; tot += lc[j]; }
            int incl = warp_suffix_incl_i(tot, lane);
            if (lane == 0) s_wi[wid] = incl;
            __syncthreads();
            if (tid < 32) {
                int wv = (lane < NW2) ? s_wi[lane] : 0;
                int wi = warp_suffix_incl_i(wv, lane);
                if (lane < NW2) s_wsuf[lane] = wi - wv;
            }
            __syncthreads();
            const int excl = (incl - tot) + s_wsuf[wid];
            if (excl < K && excl + tot >= K) {
                int cum = excl;
                #pragma unroll
                for (int j = CHB - 1; j >= 0; j--) {
                    cum += lc[j];
                    if (cum >= K) { s_tbin = base + j; break; }
                }
            }
            __syncthreads();
            const int tbin = s_tbin;

            // exact: softplus-sum above tie bin (MUFU only for ~K values); gather tie bin
            float sa = 0.f;
            int ca = 0;
            #pragma unroll
            for (int j = 0; j < CAP / T2; j++) {
                const unsigned u = v[j];
                if (tid + j * T2 < M) {
                    int bin = (int)((u >> HBSHIFT) - HBASE);
                    if (bin > HBINS - 1) bin = HBINS - 1;
                    if (bin > tbin) { sa += softplus_pos(__uint_as_float(u)); ca++; }
                    else if (bin == tbin) {
                        int pi = atomicAdd(&s_tn, 1);
                        if (pi < TIE_CAP) s_tie[pi] = u;
                    }
                }
            }
            sa = warp_sum(sa);
            ca = warp_sum_i(ca);
            if (lane == 0) { s_wf[wid] = sa; s_wi[wid] = ca; }
            __syncthreads();
            if (tid == 0) {
                float fs = 0.f; int cs = 0;
                #pragma unroll
                for (int i = 0; i < NW2; i++) { fs += s_wf[i]; cs += s_wi[i]; }
                int kr = K - cs;
                const int tn = s_tn;
                float tadd = 0.f;
                if (kr > 0) {
                    if (tn <= TIE_CAP) {
                        for (int a2 = 0; a2 < kr; a2++) {   // exact top-kr of tiny tie set
                            int mi = a2;
                            for (int z = a2 + 1; z < tn; z++)
                                if (s_tie[z] > s_tie[mi]) mi = z;
                            unsigned tv = s_tie[mi];
                            s_tie[mi] = s_tie[a2];
                            s_tie[a2] = tv;
                            tadd += softplus_pos(__uint_as_float(tv));
                        }
                    } else {
                        float ts = 0.f;
                        for (int z = 0; z < TIE_CAP; z++) ts += softplus_pos(__uint_as_float(s_tie[z]));
                        tadd = (float)kr * (ts / (float)TIE_CAP);
                    }
                }
                s_top = fs + tadd;
            }
            __syncthreads();
        } else {
            // ---- Exact fallback: binary search on mapped x-bits over full row ----
            const float4* pl4 = (const float4*)(plabels + (size_t)row * NANCH);
            const float4* gl4 = (const float4*)(glabels + (size_t)row * NANCH);
            int K_eff = NANCH - pos_num;
            if (K < K_eff) K_eff = K;
            if (K_eff > 0) {
                if (tid == 0) { s_lo = 0u; s_hi = 0xFFFFFFFFu; }
                __syncthreads();
                for (int s = 0; s < 64; s++) {
                    const unsigned lo = s_lo, hi = s_hi;
                    const unsigned w = hi - lo;
                    if (w <= 1u) break;
                    const unsigned bmid = lo + (w >> 1);
                    int c1 = 0;
                    for (int i4 = tid; i4 < NQ; i4 += T2) {
                        float4 xq = pl4[i4];
                        float4 yq = gl4[i4];
                        #pragma unroll
                        for (int c = 0; c < 4; c++) {
                            float x = (c == 0) ? xq.x : (c == 1) ? xq.y : (c == 2) ? xq.z : xq.w;
                            float y = (c == 0) ? yq.x : (c == 1) ? yq.y : (c == 2) ? yq.z : yq.w;
                            if (!(y > 0.f)) c1 += (fmap(__float_as_uint(x)) >= bmid);
                        }
                    }
                    c1 = warp_sum_i(c1);
                    if (lane == 0) s_wi[wid] = c1;
                    __syncthreads();
                    if (tid == 0) {
                        int t = 0;
                        #pragma unroll
                        for (int i = 0; i < NW2; i++) t += s_wi[i];
                        if (t >= K_eff) s_lo = bmid; else s_hi = bmid;
                    }
                    __syncthreads();
                }
                const unsigned lo = s_lo;
                float sa = 0.f;
                int ca = 0;
                for (int i4 = tid; i4 < NQ; i4 += T2) {
                    float4 xq = pl4[i4];
                    float4 yq = gl4[i4];
                    #pragma unroll
                    for (int c = 0; c < 4; c++) {
                        float x = (c == 0) ? xq.x : (c == 1) ? xq.y : (c == 2) ? xq.z : xq.w;
                        float y = (c == 0) ? yq.x : (c == 1) ? yq.y : (c == 2) ? yq.z : yq.w;
                        if (!(y > 0.f) && fmap(__float_as_uint(x)) > lo) { sa += bce_of(x, 0.f); ca++; }
                    }
                }
                sa = warp_sum(sa);
                ca = warp_sum_i(ca);
                if (lane == 0) { s_wf[wid] = sa; s_wi[wid] = ca; }
                __syncthreads();
                if (tid == 0) {
                    float fs = 0.f; int cs = 0;
                    #pragma unroll
                    for (int i = 0; i < NW2; i++) { fs += s_wf[i]; cs += s_wi[i]; }
                    float xlo = (lo & 0x80000000u) ? __uint_as_float(lo & 0x7FFFFFFFu)
                                                   : __uint_as_float(~lo);
                    s_top = fs + (float)(K_eff - cs) * bce_of(xlo, 0.f);
                }
                __syncthreads();
            }
        }
    }
    __syncthreads();

    // publish row; last block does the final reduction + scratch reset
    if (tid == 0) {
        g_row_lossl[row] = g_row_bcepos[row] + s_top;
        __threadfence();
        int prev = atomicAdd(&g_done, 1);
        s_last = (prev == BATCH - 1);
    }
    __syncthreads();
    if (!s_last) return;
    __threadfence();

    {
        float vlb = 0.f, vll = 0.f, vm = 0.f;
        if (tid < BATCH) {
            float pn  = (float)((volatile int*)g_row_posn)[tid];
            float lbv = ((volatile float*)g_row_lossb)[tid];
            float llv = ((volatile float*)g_row_lossl)[tid];
            float mask = (pn > 0.f) ? 1.f : 0.f;
            float wgt  = mask / fmaxf(pn, FLT_EPS_);
            vlb = lbv * wgt;
            vll = llv * wgt;
            vm  = wgt;
            // reset per-row scratch for the next graph replay
            g_row_posn[tid]   = 0;
            g_row_lossb[tid]  = 0.f;
            g_row_bcepos[tid] = 0.f;
            g_cand_n[tid]     = 0;
            g_row_ovf[tid]    = 0;
        }
        vlb = warp_sum(vlb);
        vll = warp_sum(vll);
        vm  = warp_sum(vm);
        if (lane == 0) {
            s_red[wid * 3 + 0] = vlb;
            s_red[wid * 3 + 1] = vll;
            s_red[wid * 3 + 2] = vm;
        }
        __syncthreads();
        if (tid == 0) {
            float slb = 0.f, sll = 0.f, sm = 0.f;
            #pragma unroll
            for (int w = 0; w < NW2; w++) {
                slb += s_red[w * 3 + 0];
                sll += s_red[w * 3 + 1];
                sm  += s_red[w * 3 + 2];
            }
            const float lb = slb / (float)BATCH;
            const float ll = sll / (float)BATCH;
            const float total = (lb + ll) * (sm / (float)BATCH);
            if (out_size >= 1) out[0] = total;
            if (out_size >= 2) out[1] = lb;
            if (out_size >= 3) out[2] = ll;
            g_done = 0;
        }
    }
}

extern "C" void kernel_launch(void* const* d_in, const int* in_sizes, int n_in,
                              void* d_out, int out_size) {
    const float* pbboxs  = (const float*)d_in[0];
    const float* plabels = (const float*)d_in[1];
    const float* gbboxs  = (const float*)d_in[2];
    const float* glabels = (const float*)d_in[3];
    const float* ancs    = (const float*)d_in[4];
    (void)in_sizes; (void)n_in;

    dim3 grid1(CHUNKS, BATCH);
    od_stream<<<grid1, T1>>>(pbboxs, plabels, gbboxs, glabels, ancs);
    od_select<<<BATCH, T2>>>(plabels, glabels, (float*)d_out, out_size);
}

// round 13
// speedup vs baseline: 1.7375x; 1.7375x over previous
#include <cuda_runtime.h>
#include <stdint.h>

#define BATCH 128
#define NANCH 16800
#define NQ 4200               // float4 per row
#define T 1024
#define NW 32
#define NIT 5                 // ceil(NQ / T)
#define NEG_RATIO 3
#define SCALE_XY 10.0f
#define SCALE_WH 5.0f
#define CAP 4096
#define PCAP 1024
#define XCF 1.1f              // x cutoff (softplus monotone; K-th x ~1.55)
#define HBSHIFT 13
#define HBINS 4096            // bins over x in [1.0, 16.0)
#define HBASE (0x3F800000u >> HBSHIFT)
#define CHB 4                 // HBINS / T
#define TIE_CAP 64
#define FLT_EPS_ 1.1920929e-07f

// Cross-block scratch (allocation-free rule: __device__ globals)
__device__ float g_row_lossb[BATCH];
__device__ float g_row_lossl[BATCH];
__device__ int   g_row_posn[BATCH];
__device__ int   g_done = 0;

__device__ __forceinline__ float warp_sum(float v) {
    #pragma unroll
    for (int o = 16; o > 0; o >>= 1) v += __shfl_down_sync(0xFFFFFFFFu, v, o);
    return v;
}
__device__ __forceinline__ int warp_sum_i(int v) {
    #pragma unroll
    for (int o = 16; o > 0; o >>= 1) v += __shfl_down_sync(0xFFFFFFFFu, v, o);
    return v;
}
__device__ __forceinline__ int warp_suffix_incl_i(int v, int lane) {
    #pragma unroll
    for (int o = 1; o < 32; o <<= 1) {
        int u = __shfl_down_sync(0xFFFFFFFFu, v, o);
        if (lane + o < 32) v += u;
    }
    return v;
}
__device__ __forceinline__ float bce_of(float x, float y) {
    return fmaxf(x, 0.f) - x * y + __logf(1.f + __expf(-fabsf(x)));
}
__device__ __forceinline__ float softplus_pos(float x) {   // bce for negative, x>0
    return x + __logf(1.f + __expf(-x));
}
__device__ __forceinline__ unsigned fmap(unsigned b) {     // order-preserving signed map
    return (b & 0x80000000u) ? ~b : (b | 0x80000000u);
}

__global__ __launch_bounds__(T, 1)
void od_fused(const float* __restrict__ pbboxs,
              const float* __restrict__ plabels,
              const float* __restrict__ gbboxs,
              const float* __restrict__ glabels,
              const float* __restrict__ ancs,
              float* __restrict__ out, int out_size) {
    const int b    = blockIdx.x;
    const int tid  = threadIdx.x;
    const int lane = tid & 31;
    const int wid  = tid >> 5;

    __shared__ unsigned s_cand[CAP];     // candidate x bit patterns (16 KB)
    __shared__ int      s_pidx[PCAP];    // positive element indices (4 KB)
    __shared__ int      s_hist[HBINS];   // 16 KB
    __shared__ unsigned s_tie[TIE_CAP];
    __shared__ float    s_wf[NW], s_wf2[NW];
    __shared__ int      s_wi[NW], s_wsuf[NW];
    __shared__ float    s_sl1, s_bce, s_top;
    __shared__ int      s_m, s_np, s_ovf, s_povf, s_tn, s_tbin, s_last;
    __shared__ unsigned s_lo, s_hi;
    __shared__ float    s_red[NW * 3];

    #pragma unroll
    for (int j = 0; j < CHB; j++) s_hist[tid + j * T] = 0;
    if (tid == 0) { s_m = 0; s_np = 0; s_ovf = 0; s_povf = 0; s_tn = 0; s_top = 0.f; s_tbin = 0; }
    __syncthreads();

    const float*  plr = plabels + (size_t)b * NANCH;
    const float*  glr = glabels + (size_t)b * NANCH;
    const float4* pl4 = (const float4*)plr;
    const float4* gl4 = (const float4*)glr;
    const float4* pb  = (const float4*)pbboxs + (size_t)b * NANCH;
    const float4* gb  = (const float4*)gbboxs + (size_t)b * NANCH;
    const float4* an  = (const float4*)ancs;

    // ---- Main pass: pure streaming — compares + ballots only ----
    float4 xv = make_float4(0.f, 0.f, 0.f, 0.f);
    float4 yv = make_float4(0.f, 0.f, 0.f, 0.f);
    if (tid < NQ) { xv = pl4[tid]; yv = gl4[tid]; }
    #pragma unroll
    for (int it = 0; it < NIT; it++) {
        float4 xn = make_float4(0.f, 0.f, 0.f, 0.f);
        float4 yn = make_float4(0.f, 0.f, 0.f, 0.f);
        if (it + 1 < NIT) {
            const int i4n = tid + (it + 1) * T;
            if (i4n < NQ) { xn = pl4[i4n]; yn = gl4[i4n]; }
        }
        const int i4 = tid + it * T;

        float xs[4];
        bool  pos[4], cand[4];
        #pragma unroll
        for (int c = 0; c < 4; c++) {
            float x = (c == 0) ? xv.x : (c == 1) ? xv.y : (c == 2) ? xv.z : xv.w;
            float y = (c == 0) ? yv.x : (c == 1) ? yv.y : (c == 2) ? yv.z : yv.w;
            xs[c]   = x;
            pos[c]  = (y > 0.f);               // tail: y=0 -> never
            cand[c] = (!pos[c]) && (x >= XCF); // tail: x=0 -> never
        }
        // candidates -> s_cand (x bits; x>0 so bit order == value order)
        unsigned mc0 = __ballot_sync(0xFFFFFFFFu, cand[0]);
        unsigned mc1 = __ballot_sync(0xFFFFFFFFu, cand[1]);
        unsigned mc2 = __ballot_sync(0xFFFFFFFFu, cand[2]);
        unsigned mc3 = __ballot_sync(0xFFFFFFFFu, cand[3]);
        int wc = __popc(mc0) + __popc(mc1) + __popc(mc2) + __popc(mc3);
        if (wc > 0) {
            int base = 0;
            if (lane == 0) base = atomicAdd(&s_m, wc);
            base = __shfl_sync(0xFFFFFFFFu, base, 0);
            const unsigned lm = (1u << lane) - 1u;
            int off = base;
            if (cand[0]) { int pi = off + __popc(mc0 & lm); if (pi < CAP) s_cand[pi] = __float_as_uint(xs[0]); else s_ovf = 1; }
            off += __popc(mc0);
            if (cand[1]) { int pi = off + __popc(mc1 & lm); if (pi < CAP) s_cand[pi] = __float_as_uint(xs[1]); else s_ovf = 1; }
            off += __popc(mc1);
            if (cand[2]) { int pi = off + __popc(mc2 & lm); if (pi < CAP) s_cand[pi] = __float_as_uint(xs[2]); else s_ovf = 1; }
            off += __popc(mc2);
            if (cand[3]) { int pi = off + __popc(mc3 & lm); if (pi < CAP) s_cand[pi] = __float_as_uint(xs[3]); else s_ovf = 1; }
        }
        // positives -> s_pidx (element indices; processed in batched phase below)
        unsigned mp0 = __ballot_sync(0xFFFFFFFFu, pos[0]);
        unsigned mp1 = __ballot_sync(0xFFFFFFFFu, pos[1]);
        unsigned mp2 = __ballot_sync(0xFFFFFFFFu, pos[2]);
        unsigned mp3 = __ballot_sync(0xFFFFFFFFu, pos[3]);
        int wp = __popc(mp0) + __popc(mp1) + __popc(mp2) + __popc(mp3);
        if (wp > 0) {
            int base = 0;
            if (lane == 0) base = atomicAdd(&s_np, wp);
            base = __shfl_sync(0xFFFFFFFFu, base, 0);
            const unsigned lm = (1u << lane) - 1u;
            const int ei = i4 << 2;
            int off = base;
            if (pos[0]) { int pi = off + __popc(mp0 & lm); if (pi < PCAP) s_pidx[pi] = ei + 0; else s_povf = 1; }
            off += __popc(mp0);
            if (pos[1]) { int pi = off + __popc(mp1 & lm); if (pi < PCAP) s_pidx[pi] = ei + 1; else s_povf = 1; }
            off += __popc(mp1);
            if (pos[2]) { int pi = off + __popc(mp2 & lm); if (pi < PCAP) s_pidx[pi] = ei + 2; else s_povf = 1; }
            off += __popc(mp2);
            if (pos[3]) { int pi = off + __popc(mp3 & lm); if (pi < PCAP) s_pidx[pi] = ei + 3; else s_povf = 1; }
        }
        xv = xn; yv = yn;
    }
    __syncthreads();

    const int pos_num = s_np;
    const int M = s_m;
    const bool ovf = (s_ovf != 0);

    // ---- Positive phase: batched gather, one latency exposure ----
    float acc_sl1 = 0.f, acc_bce = 0.f;
    if (s_povf == 0) {
        for (int t = tid; t < pos_num; t += T) {
            const int i = s_pidx[t];
            float x = plr[i];
            float y = glr[i];
            acc_bce += bce_of(x, y);
            float4 p = pb[i];
            float4 g = gb[i];
            float4 a = an[i];
            float inv_az = 1.f / a.z;
            float inv_aw = 1.f / a.w;
            float d0 = p.x - SCALE_XY * (g.x - a.x) * inv_az;
            float d1 = p.y - SCALE_XY * (g.y - a.y) * inv_aw;
            float d2 = p.z - SCALE_WH * __logf(g.z * inv_az);
            float d3 = p.w - SCALE_WH * __logf(g.w * inv_aw);
            float ad;
            ad = fabsf(d0); acc_sl1 += (ad < 1.f) ? 0.5f * d0 * d0 : ad - 0.5f;
            ad = fabsf(d1); acc_sl1 += (ad < 1.f) ? 0.5f * d1 * d1 : ad - 0.5f;
            ad = fabsf(d2); acc_sl1 += (ad < 1.f) ? 0.5f * d2 * d2 : ad - 0.5f;
            ad = fabsf(d3); acc_sl1 += (ad < 1.f) ? 0.5f * d3 * d3 : ad - 0.5f;
        }
    } else {
        // overflow fallback (statistically never): full rescan for positives
        for (int i = tid; i < NANCH; i += T) {
            float y = glr[i];
            if (y > 0.f) {
                float x = plr[i];
                acc_bce += bce_of(x, y);
                float4 p = pb[i];
                float4 g = gb[i];
                float4 a = an[i];
                float inv_az = 1.f / a.z;
                float inv_aw = 1.f / a.w;
                float d0 = p.x - SCALE_XY * (g.x - a.x) * inv_az;
                float d1 = p.y - SCALE_XY * (g.y - a.y) * inv_aw;
                float d2 = p.z - SCALE_WH * __logf(g.z * inv_az);
                float d3 = p.w - SCALE_WH * __logf(g.w * inv_aw);
                float ad;
                ad = fabsf(d0); acc_sl1 += (ad < 1.f) ? 0.5f * d0 * d0 : ad - 0.5f;
                ad = fabsf(d1); acc_sl1 += (ad < 1.f) ? 0.5f * d1 * d1 : ad - 0.5f;
                ad = fabsf(d2); acc_sl1 += (ad < 1.f) ? 0.5f * d2 * d2 : ad - 0.5f;
                ad = fabsf(d3); acc_sl1 += (ad < 1.f) ? 0.5f * d3 * d3 : ad - 0.5f;
            }
        }
    }
    {
        float w1 = warp_sum(acc_sl1);
        float w2 = warp_sum(acc_bce);
        if (lane == 0) { s_wf[wid] = w1; s_wf2[wid] = w2; }
    }
    __syncthreads();
    if (tid < 32) {
        float v1 = warp_sum(s_wf[lane]);
        float v2 = warp_sum(s_wf2[lane]);
        if (lane == 0) { s_sl1 = v1; s_bce = v2; }
    }
    __syncthreads();

    int K = NEG_RATIO * pos_num;
    if (K > NANCH) K = NANCH;

    if (K > 0) {
        if (!ovf && M >= K) {
            // ---- Exact top-K: histogram on candidate x-bits + suffix-scan ----
            for (int idx = tid; idx < M; idx += T) {
                unsigned u = s_cand[idx];
                unsigned bin = (u >> HBSHIFT) - HBASE;
                if (bin > HBINS - 1) bin = HBINS - 1;
                atomicAdd(&s_hist[bin], 1);
            }
            __syncthreads();

            const int base = tid * CHB;
            int lc[CHB];
            int tot = 0;
            #pragma unroll
            for (int j = 0; j < CHB; j++) { lc[j] = s_hist[base + j]; tot += lc[j]; }
            int incl = warp_suffix_incl_i(tot, lane);
            if (lane == 0) s_wi[wid] = incl;
            __syncthreads();
            if (tid < 32) {
                int wv = s_wi[lane];
                int wi = warp_suffix_incl_i(wv, lane);
                s_wsuf[lane] = wi - wv;
            }
            __syncthreads();
            const int excl = (incl - tot) + s_wsuf[wid];
            if (excl < K && excl + tot >= K) {
                int cum = excl;
                #pragma unroll
                for (int j = CHB - 1; j >= 0; j--) {
                    cum += lc[j];
                    if (cum >= K) { s_tbin = base + j; break; }
                }
            }
            __syncthreads();
            const int tbin = s_tbin;

            // exact: softplus-sum above tie bin; gather tie-bin values
            float sa = 0.f;
            int ca = 0;
            for (int idx = tid; idx < M; idx += T) {
                unsigned u = s_cand[idx];
                int bin = (int)((u >> HBSHIFT) - HBASE);
                if (bin > HBINS - 1) bin = HBINS - 1;
                if (bin > tbin) { sa += softplus_pos(__uint_as_float(u)); ca++; }
                else if (bin == tbin) {
                    int pi = atomicAdd(&s_tn, 1);
                    if (pi < TIE_CAP) s_tie[pi] = u;
                }
            }
            sa = warp_sum(sa);
            ca = warp_sum_i(ca);
            if (lane == 0) { s_wf[wid] = sa; s_wi[wid] = ca; }
            __syncthreads();
            if (tid == 0) {
                float fs = 0.f; int cs = 0;
                #pragma unroll
                for (int i = 0; i < NW; i++) { fs += s_wf[i]; cs += s_wi[i]; }
                int kr = K - cs;
                const int tn = s_tn;
                float tadd = 0.f;
                if (kr > 0) {
                    if (tn <= TIE_CAP) {
                        for (int a2 = 0; a2 < kr; a2++) {   // exact top-kr of tiny tie set
                            int mi = a2;
                            for (int z = a2 + 1; z < tn; z++)
                                if (s_tie[z] > s_tie[mi]) mi = z;
                            unsigned tv = s_tie[mi];
                            s_tie[mi] = s_tie[a2];
                            s_tie[a2] = tv;
                            tadd += softplus_pos(__uint_as_float(tv));
                        }
                    } else {
                        float ts = 0.f;
                        for (int z = 0; z < TIE_CAP; z++) ts += softplus_pos(__uint_as_float(s_tie[z]));
                        tadd = (float)kr * (ts / (float)TIE_CAP);
                    }
                }
                s_top = fs + tadd;
            }
            __syncthreads();
        } else {
            // ---- Exact fallback: binary search on mapped x-bits (never taken) ----
            int K_eff = NANCH - pos_num;
            if (K < K_eff) K_eff = K;
            if (K_eff > 0) {
                if (tid == 0) { s_lo = 0u; s_hi = 0xFFFFFFFFu; }
                __syncthreads();
                for (int s = 0; s < 64; s++) {
                    const unsigned lo = s_lo, hi = s_hi;
                    const unsigned w = hi - lo;
                    if (w <= 1u) break;
                    const unsigned bmid = lo + (w >> 1);
                    int c1 = 0;
                    for (int i4 = tid; i4 < NQ; i4 += T) {
                        float4 xq = pl4[i4];
                        float4 yq = gl4[i4];
                        #pragma unroll
                        for (int c = 0; c < 4; c++) {
                            float x = (c == 0) ? xq.x : (c == 1) ? xq.y : (c == 2) ? xq.z : xq.w;
                            float y = (c == 0) ? yq.x : (c == 1) ? yq.y : (c == 2) ? yq.z : yq.w;
                            if (!(y > 0.f)) c1 += (fmap(__float_as_uint(x)) >= bmid);
                        }
                    }
                    c1 = warp_sum_i(c1);
                    if (lane == 0) s_wi[wid] = c1;
                    __syncthreads();
                    if (tid == 0) {
                        int t = 0;
                        #pragma unroll
                        for (int i = 0; i < NW; i++) t += s_wi[i];
                        if (t >= K_eff) s_lo = bmid; else s_hi = bmid;
                    }
                    __syncthreads();
                }
                const unsigned lo = s_lo;
                float sa = 0.f;
                int ca = 0;
                for (int i4 = tid; i4 < NQ; i4 += T) {
                    float4 xq = pl4[i4];
                    float4 yq = gl4[i4];
                    #pragma unroll
                    for (int c = 0; c < 4; c++) {
                        float x = (c == 0) ? xq.x : (c == 1) ? xq.y : (c == 2) ? xq.z : xq.w;
                        float y = (c == 0) ? yq.x : (c == 1) ? yq.y : (c == 2) ? yq.z : yq.w;
                        if (!(y > 0.f) && fmap(__float_as_uint(x)) > lo) { sa += bce_of(x, 0.f); ca++; }
                    }
                }
                sa = warp_sum(sa);
                ca = warp_sum_i(ca);
                if (lane == 0) { s_wf[wid] = sa; s_wi[wid] = ca; }
                __syncthreads();
                if (tid == 0) {
                    float fs = 0.f; int cs = 0;
                    #pragma unroll
                    for (int i = 0; i < NW; i++) { fs += s_wf[i]; cs += s_wi[i]; }
                    float xlo = (lo & 0x80000000u) ? __uint_as_float(lo & 0x7FFFFFFFu)
                                                   : __uint_as_float(~lo);
                    s_top = fs + (float)(K_eff - cs) * bce_of(xlo, 0.f);
                }
                __syncthreads();
            }
        }
    }
    const float sum_top = (K > 0) ? s_top : 0.f;

    // ---- Publish row; last block does the final reduction ----
    if (tid == 0) {
        g_row_posn[b]  = pos_num;
        g_row_lossb[b] = s_sl1;
        g_row_lossl[b] = s_bce + sum_top;
        __threadfence();
        int prev = atomicAdd(&g_done, 1);
        s_last = (prev == BATCH - 1);
    }
    __syncthreads();

    if (s_last) {
        float vlb = 0.f, vll = 0.f, vm = 0.f;
        if (tid < BATCH) {
            float pn  = (float)((volatile int*)g_row_posn)[tid];
            float lbv = ((volatile float*)g_row_lossb)[tid];
            float llv = ((volatile float*)g_row_lossl)[tid];
            float mask = (pn > 0.f) ? 1.f : 0.f;
            float wgt  = mask / fmaxf(pn, FLT_EPS_);
            vlb = lbv * wgt;
            vll = llv * wgt;
            vm  = wgt;
        }
        vlb = warp_sum(vlb);
        vll = warp_sum(vll);
        vm  = warp_sum(vm);
        if (lane == 0) {
            s_red[wid * 3 + 0] = vlb;
            s_red[wid * 3 + 1] = vll;
            s_red[wid * 3 + 2] = vm;
        }
        __syncthreads();
        if (tid == 0) {
            float slb = 0.f, sll = 0.f, sm = 0.f;
            #pragma unroll
            for (int w = 0; w < NW; w++) {
                slb += s_red[w * 3 + 0];
                sll += s_red[w * 3 + 1];
                sm  += s_red[w * 3 + 2];
            }
            const float lb = slb / (float)BATCH;
            const float ll = sll / (float)BATCH;
            const float total = (lb + ll) * (sm / (float)BATCH);
            if (out_size >= 1) out[0] = total;
            if (out_size >= 2) out[1] = lb;
            if (out_size >= 3) out[2] = ll;
            g_done = 0;  // reset for next graph replay
        }
    }
}

extern "C" void kernel_launch(void* const* d_in, const int* in_sizes, int n_in,
                              void* d_out, int out_size) {
    const float* pbboxs  = (const float*)d_in[0];
    const float* plabels = (const float*)d_in[1];
    const float* gbboxs  = (const float*)d_in[2];
    const float* glabels = (const float*)d_in[3];
    const float* ancs    = (const float*)d_in[4];
    (void)in_sizes; (void)n_in;

    od_fused<<<BATCH, T>>>(pbboxs, plabels, gbboxs, glabels, ancs,
                           (float*)d_out, out_size);
}